// round 16
// baseline (speedup 1.0000x reference)
#include <cuda_runtime.h>

// ---------------------------------------------------------------------------
// MHA: out = (softmax(scale * (xq Wq + bq)(xk Wk + bk)^T masked) (xv Wv + bv)) Wo + bo
// Shapes: B=2, Tq=Tk=2048, D=1024, H=16, dh=64.
// d_out = [ out (B*Tq*D = 4194304 f32) | attn (B*H*Tq*Tk = 134217728 f32) ]
// ---------------------------------------------------------------------------

#define D_MODEL 1024
#define NHEADS  16
#define DHEAD   64
#define BATCH   2
#define SEQQ    2048
#define SEQK    2048
#define MTOK    (BATCH * SEQQ)          // 4096 rows for projection GEMMs

static __device__ float g_q[(size_t)MTOK * D_MODEL];
static __device__ float g_k[(size_t)MTOK * D_MODEL];
static __device__ float g_v[(size_t)MTOK * D_MODEL];
static __device__ float g_ctx[(size_t)MTOK * D_MODEL];
// Fallback scratch for attn if the harness only checks `out`.
static __device__ float g_attn[(size_t)BATCH * NHEADS * SEQQ * SEQK];

// ---------------------------------------------------------------------------
// C[M,N] = A[M,K] @ W[K,N] + bias[N]   (all row-major, fp32)
// 128x128 tile, BK=8, 256 threads, 8x8 per thread.
// ---------------------------------------------------------------------------
__global__ __launch_bounds__(256) void gemm_bias_128x128(
    const float* __restrict__ A, const float* __restrict__ W,
    const float* __restrict__ bias, float* __restrict__ C,
    int M, int N, int K)
{
    constexpr int BM = 128, BN = 128, BK = 8, TM = 8, TN = 8;
    __shared__ float As[BK][BM];
    __shared__ float Bs[BK][BN];

    const int tid  = threadIdx.x;
    const int tRow = tid >> 4;          // 0..15
    const int tCol = tid & 15;          // 0..15
    const int aRow = tid >> 1;          // 0..127
    const int aCol = (tid & 1) * 4;     // 0 or 4
    const int bRow = tid >> 5;          // 0..7
    const int bCol = (tid & 31) * 4;    // 0..124

    const float* Ab = A + (size_t)blockIdx.y * BM * K;
    const float* Wb = W + (size_t)blockIdx.x * BN;

    float acc[TM][TN] = {};

    for (int k0 = 0; k0 < K; k0 += BK) {
        float4 a4 = *(const float4*)(Ab + (size_t)aRow * K + k0 + aCol);
        As[aCol + 0][aRow] = a4.x;
        As[aCol + 1][aRow] = a4.y;
        As[aCol + 2][aRow] = a4.z;
        As[aCol + 3][aRow] = a4.w;
        *(float4*)&Bs[bRow][bCol] =
            *(const float4*)(Wb + (size_t)(k0 + bRow) * N + bCol);
        __syncthreads();

#pragma unroll
        for (int k = 0; k < BK; k++) {
            float regM[TM], regN[TN];
            *(float4*)&regM[0] = *(const float4*)&As[k][tRow * TM];
            *(float4*)&regM[4] = *(const float4*)&As[k][tRow * TM + 4];
            *(float4*)&regN[0] = *(const float4*)&Bs[k][tCol * TN];
            *(float4*)&regN[4] = *(const float4*)&Bs[k][tCol * TN + 4];
#pragma unroll
            for (int i = 0; i < TM; i++)
#pragma unroll
                for (int j = 0; j < TN; j++)
                    acc[i][j] += regM[i] * regN[j];
        }
        __syncthreads();
    }

    const int rowBase = blockIdx.y * BM + tRow * TM;
    const int colBase = blockIdx.x * BN + tCol * TN;
#pragma unroll
    for (int i = 0; i < TM; i++) {
#pragma unroll
        for (int j = 0; j < TN; j += 4) {
            float4 o;
            o.x = acc[i][j + 0] + bias[colBase + j + 0];
            o.y = acc[i][j + 1] + bias[colBase + j + 1];
            o.z = acc[i][j + 2] + bias[colBase + j + 2];
            o.w = acc[i][j + 3] + bias[colBase + j + 3];
            *(float4*)(C + (size_t)(rowBase + i) * N + colBase + j) = o;
        }
    }
}

// ---------------------------------------------------------------------------
// scores: S[bh, q, k] = scale * dot(Q[b,q,h,:], K[b,k,h,:]), masked.
// Q/K live in g_q/g_k as [B*T, D_MODEL]; head h = cols [h*64, h*64+64).
// 128x128 tile over (q,k), K-dim = 64 processed in two 32-chunks.
// ---------------------------------------------------------------------------
__global__ __launch_bounds__(256) void scores_kernel(
    const int* __restrict__ mask, float* __restrict__ Sext, int use_ext)
{
    constexpr int BM = 128, BN = 128, BK = 32, TM = 8, TN = 8;
    __shared__ float Qs[BK][BM];
    __shared__ float Ks[BK][BN];

    float* S = use_ext ? Sext : g_attn;
    const int bh = blockIdx.z;
    const int b  = bh >> 4;
    const int h  = bh & 15;
    const int tid  = threadIdx.x;
    const int tRow = tid >> 4;
    const int tCol = tid & 15;

    const float* Qb = g_q + ((size_t)b * SEQQ + (size_t)blockIdx.y * BM) * D_MODEL + h * DHEAD;
    const float* Kb = g_k + ((size_t)b * SEQK + (size_t)blockIdx.x * BN) * D_MODEL + h * DHEAD;

    float acc[TM][TN] = {};

    for (int k0 = 0; k0 < DHEAD; k0 += BK) {
        // 128 rows x 32 cols per operand = 1024 float4 -> 4 per thread each
#pragma unroll
        for (int i = 0; i < 4; i++) {
            int idx = tid + i * 256;
            int row = idx >> 3;          // 8 float4 per row
            int cv  = (idx & 7) * 4;
            float4 q4 = *(const float4*)(Qb + (size_t)row * D_MODEL + k0 + cv);
            Qs[cv + 0][row] = q4.x; Qs[cv + 1][row] = q4.y;
            Qs[cv + 2][row] = q4.z; Qs[cv + 3][row] = q4.w;
            float4 k4 = *(const float4*)(Kb + (size_t)row * D_MODEL + k0 + cv);
            Ks[cv + 0][row] = k4.x; Ks[cv + 1][row] = k4.y;
            Ks[cv + 2][row] = k4.z; Ks[cv + 3][row] = k4.w;
        }
        __syncthreads();

#pragma unroll
        for (int k = 0; k < BK; k++) {
            float regM[TM], regN[TN];
            *(float4*)&regM[0] = *(const float4*)&Qs[k][tRow * TM];
            *(float4*)&regM[4] = *(const float4*)&Qs[k][tRow * TM + 4];
            *(float4*)&regN[0] = *(const float4*)&Ks[k][tCol * TN];
            *(float4*)&regN[4] = *(const float4*)&Ks[k][tCol * TN + 4];
#pragma unroll
            for (int i = 0; i < TM; i++)
#pragma unroll
                for (int j = 0; j < TN; j++)
                    acc[i][j] += regM[i] * regN[j];
        }
        __syncthreads();
    }

    const float scale = 0.125f;  // 64^-0.5
    const int q0 = blockIdx.y * BM + tRow * TM;
    const int c0 = blockIdx.x * BN + tCol * TN;
#pragma unroll
    for (int i = 0; i < TM; i++) {
        const int q = q0 + i;
        const size_t mrow = ((size_t)b * SEQQ + q) * SEQK;
        const size_t srow = ((size_t)bh * SEQQ + q) * SEQK;
#pragma unroll
        for (int j = 0; j < TN; j += 4) {
            int4 mk = *(const int4*)(mask + mrow + c0 + j);
            float4 o;
            o.x = mk.x ? acc[i][j + 0] * scale : -1e30f;
            o.y = mk.y ? acc[i][j + 1] * scale : -1e30f;
            o.z = mk.z ? acc[i][j + 2] * scale : -1e30f;
            o.w = mk.w ? acc[i][j + 3] * scale : -1e30f;
            *(float4*)(S + srow + c0 + j) = o;
        }
    }
}

// ---------------------------------------------------------------------------
// In-place row softmax over the last dim (2048). One block (256 thr) per row.
// ---------------------------------------------------------------------------
__global__ __launch_bounds__(256) void softmax_kernel(float* __restrict__ Sext, int use_ext)
{
    float* S = use_ext ? Sext : g_attn;
    float* p = S + (size_t)blockIdx.x * SEQK;
    const int tid = threadIdx.x;

    float4 v0 = *(float4*)(p + tid * 8);
    float4 v1 = *(float4*)(p + tid * 8 + 4);

    float m = fmaxf(fmaxf(fmaxf(v0.x, v0.y), fmaxf(v0.z, v0.w)),
                    fmaxf(fmaxf(v1.x, v1.y), fmaxf(v1.z, v1.w)));

    __shared__ float redmax[8];
    __shared__ float redsum[8];
#pragma unroll
    for (int o = 16; o; o >>= 1) m = fmaxf(m, __shfl_xor_sync(0xffffffffu, m, o));
    if ((tid & 31) == 0) redmax[tid >> 5] = m;
    __syncthreads();
    float mm = redmax[0];
#pragma unroll
    for (int i = 1; i < 8; i++) mm = fmaxf(mm, redmax[i]);

    v0.x = __expf(v0.x - mm); v0.y = __expf(v0.y - mm);
    v0.z = __expf(v0.z - mm); v0.w = __expf(v0.w - mm);
    v1.x = __expf(v1.x - mm); v1.y = __expf(v1.y - mm);
    v1.z = __expf(v1.z - mm); v1.w = __expf(v1.w - mm);

    float s = (v0.x + v0.y) + (v0.z + v0.w) + (v1.x + v1.y) + (v1.z + v1.w);
#pragma unroll
    for (int o = 16; o; o >>= 1) s += __shfl_xor_sync(0xffffffffu, s, o);
    if ((tid & 31) == 0) redsum[tid >> 5] = s;
    __syncthreads();
    float ss = 0.f;
#pragma unroll
    for (int i = 0; i < 8; i++) ss += redsum[i];
    const float inv = 1.0f / ss;

    v0.x *= inv; v0.y *= inv; v0.z *= inv; v0.w *= inv;
    v1.x *= inv; v1.y *= inv; v1.z *= inv; v1.w *= inv;
    *(float4*)(p + tid * 8)     = v0;
    *(float4*)(p + tid * 8 + 4) = v1;
}

// ---------------------------------------------------------------------------
// PV: ctx[b, q, h*64+n] = sum_k attn[bh, q, k] * V[b, k, h*64+n]
// 128x64 tile, BK=16, 256 threads, 8x4 per thread.
// ---------------------------------------------------------------------------
__global__ __launch_bounds__(256) void pv_kernel(const float* __restrict__ Sext, int use_ext)
{
    constexpr int BM = 128, BN = 64, BK = 16, TM = 8, TN = 4;
    __shared__ float Ps[BK][BM];
    __shared__ float Vs[BK][BN];

    const float* S = use_ext ? Sext : g_attn;
    const int bh = blockIdx.z;
    const int b  = bh >> 4;
    const int h  = bh & 15;
    const int tid  = threadIdx.x;
    const int tRow = tid >> 4;
    const int tCol = tid & 15;

    const float* Pb = S + ((size_t)bh * SEQQ + (size_t)blockIdx.x * BM) * SEQK;
    const float* Vb = g_v + (size_t)b * SEQK * D_MODEL + h * DHEAD;

    float acc[TM][TN] = {};

    for (int k0 = 0; k0 < SEQK; k0 += BK) {
        // P tile 128x16 = 512 float4 -> 2 per thread
#pragma unroll
        for (int i = 0; i < 2; i++) {
            int idx = tid + i * 256;
            int row = idx >> 2;
            int cv  = (idx & 3) * 4;
            float4 p4 = *(const float4*)(Pb + (size_t)row * SEQK + k0 + cv);
            Ps[cv + 0][row] = p4.x; Ps[cv + 1][row] = p4.y;
            Ps[cv + 2][row] = p4.z; Ps[cv + 3][row] = p4.w;
        }
        // V tile 16x64 = 256 float4 -> 1 per thread
        {
            int row = tid >> 4;
            int cv  = (tid & 15) * 4;
            *(float4*)&Vs[row][cv] =
                *(const float4*)(Vb + (size_t)(k0 + row) * D_MODEL + cv);
        }
        __syncthreads();

#pragma unroll
        for (int k = 0; k < BK; k++) {
            float regM[TM], regN[TN];
            *(float4*)&regM[0] = *(const float4*)&Ps[k][tRow * TM];
            *(float4*)&regM[4] = *(const float4*)&Ps[k][tRow * TM + 4];
            *(float4*)&regN[0] = *(const float4*)&Vs[k][tCol * TN];
#pragma unroll
            for (int i = 0; i < TM; i++)
#pragma unroll
                for (int j = 0; j < TN; j++)
                    acc[i][j] += regM[i] * regN[j];
        }
        __syncthreads();
    }

    const int q0 = blockIdx.x * BM + tRow * TM;
    const int n0 = tCol * TN;
#pragma unroll
    for (int i = 0; i < TM; i++) {
        float4 o;
        o.x = acc[i][0]; o.y = acc[i][1]; o.z = acc[i][2]; o.w = acc[i][3];
        *(float4*)(g_ctx + ((size_t)b * SEQQ + q0 + i) * D_MODEL + h * DHEAD + n0) = o;
    }
}

// ---------------------------------------------------------------------------
extern "C" void kernel_launch(void* const* d_in, const int* in_sizes, int n_in,
                              void* d_out, int out_size)
{
    const float* q    = (const float*)d_in[0];
    const float* k    = (const float*)d_in[1];
    const float* v    = (const float*)d_in[2];
    const int*   mask = (const int*)  d_in[3];
    const float* w_q  = (const float*)d_in[4];
    const float* b_q  = (const float*)d_in[5];
    const float* w_k  = (const float*)d_in[6];
    const float* b_k  = (const float*)d_in[7];
    const float* w_v  = (const float*)d_in[8];
    const float* b_v  = (const float*)d_in[9];
    const float* w_o  = (const float*)d_in[10];
    const float* b_o  = (const float*)d_in[11];

    float* out = (float*)d_out;

    const size_t OUT_ELEMS  = (size_t)MTOK * D_MODEL;                       // 4194304
    const size_t ATTN_ELEMS = (size_t)BATCH * NHEADS * SEQQ * SEQK;         // 134217728
    const int use_ext = ((size_t)out_size >= OUT_ELEMS + ATTN_ELEMS) ? 1 : 0;
    float* attn_ext = out + OUT_ELEMS;

    float *gq = nullptr, *gk = nullptr, *gv = nullptr, *gctx = nullptr;
    cudaGetSymbolAddress((void**)&gq,  g_q);
    cudaGetSymbolAddress((void**)&gk,  g_k);
    cudaGetSymbolAddress((void**)&gv,  g_v);
    cudaGetSymbolAddress((void**)&gctx, g_ctx);

    dim3 gproj(D_MODEL / 128, MTOK / 128);               // (8, 32)
    gemm_bias_128x128<<<gproj, 256>>>(q, w_q, b_q, gq, MTOK, D_MODEL, D_MODEL);
    gemm_bias_128x128<<<gproj, 256>>>(k, w_k, b_k, gk, MTOK, D_MODEL, D_MODEL);
    gemm_bias_128x128<<<gproj, 256>>>(v, w_v, b_v, gv, MTOK, D_MODEL, D_MODEL);

    dim3 gsc(SEQK / 128, SEQQ / 128, BATCH * NHEADS);    // (16, 16, 32)
    scores_kernel<<<gsc, 256>>>(mask, attn_ext, use_ext);

    softmax_kernel<<<BATCH * NHEADS * SEQQ, 256>>>(attn_ext, use_ext);

    dim3 gpv(SEQQ / 128, 1, BATCH * NHEADS);             // (16, 1, 32)
    pv_kernel<<<gpv, 256>>>(attn_ext, use_ext);

    gemm_bias_128x128<<<gproj, 256>>>(gctx, w_o, b_o, out, MTOK, D_MODEL, D_MODEL);
}

// round 17
// speedup vs baseline: 1.0188x; 1.0188x over previous
#include <cuda_runtime.h>

// ---------------------------------------------------------------------------
// MHA: out = (softmax(scale * (xq Wq + bq)(xk Wk + bk)^T masked) (xv Wv + bv)) Wo + bo
// Shapes: B=2, Tq=Tk=2048, D=1024, H=16, dh=64.
// d_out = [ out (4194304 f32) | attn (134217728 f32) ]
//
// Pipeline (no separate softmax pass):
//   1) qkv_gemm (z=3 fused):       g_q/g_k/g_v = x @ W + b
//   2) scores_kernel:              S = exp(scale*QK^T) (masked->0), partial row sums
//   3) rowsum_reduce:              g_rowinv = 1/sum (deterministic)
//   4) pv_kernel:                  ctx = (S @ V) * inv;  attn <- S * inv (in place)
//   5) gemm_bias (out-projection)
// ---------------------------------------------------------------------------

#define D_MODEL 1024
#define NHEADS  16
#define DHEAD   64
#define BATCH   2
#define SEQQ    2048
#define SEQK    2048
#define MTOK    (BATCH * SEQQ)
#define NROWS   (BATCH * NHEADS * SEQQ)     // 65536 attention rows
#define KTILES  (SEQK / 128)                // 16 score tiles per row

static __device__ float g_q[(size_t)MTOK * D_MODEL];
static __device__ float g_k[(size_t)MTOK * D_MODEL];
static __device__ float g_v[(size_t)MTOK * D_MODEL];
static __device__ float g_ctx[(size_t)MTOK * D_MODEL];
static __device__ float g_partial[(size_t)NROWS * KTILES];
static __device__ float g_rowinv[(size_t)NROWS];
// Fallback scratch for attn if the harness only checks `out`.
static __device__ float g_attn[(size_t)BATCH * NHEADS * SEQQ * SEQK];

// ---------------------------------------------------------------------------
// Generic C[M,N] = A[M,K] @ W[K,N] + bias[N] (row-major fp32), 128x128, BK=8.
// ---------------------------------------------------------------------------
__device__ __forceinline__ void gemm_body(
    const float* __restrict__ A, const float* __restrict__ W,
    const float* __restrict__ bias, float* __restrict__ C,
    int N, int K, int bx, int by, int tid)
{
    constexpr int BM = 128, BN = 128, BK = 8, TM = 8, TN = 8;
    __shared__ float As[BK][BM];
    __shared__ float Bs[BK][BN];

    const int tRow = tid >> 4;
    const int tCol = tid & 15;
    const int aRow = tid >> 1;
    const int aCol = (tid & 1) * 4;
    const int bRow = tid >> 5;
    const int bCol = (tid & 31) * 4;

    const float* Ab = A + (size_t)by * BM * K;
    const float* Wb = W + (size_t)bx * BN;

    float acc[TM][TN] = {};

    for (int k0 = 0; k0 < K; k0 += BK) {
        float4 a4 = *(const float4*)(Ab + (size_t)aRow * K + k0 + aCol);
        As[aCol + 0][aRow] = a4.x;
        As[aCol + 1][aRow] = a4.y;
        As[aCol + 2][aRow] = a4.z;
        As[aCol + 3][aRow] = a4.w;
        *(float4*)&Bs[bRow][bCol] =
            *(const float4*)(Wb + (size_t)(k0 + bRow) * N + bCol);
        __syncthreads();

#pragma unroll
        for (int k = 0; k < BK; k++) {
            float regM[TM], regN[TN];
            *(float4*)&regM[0] = *(const float4*)&As[k][tRow * TM];
            *(float4*)&regM[4] = *(const float4*)&As[k][tRow * TM + 4];
            *(float4*)&regN[0] = *(const float4*)&Bs[k][tCol * TN];
            *(float4*)&regN[4] = *(const float4*)&Bs[k][tCol * TN + 4];
#pragma unroll
            for (int i = 0; i < TM; i++)
#pragma unroll
                for (int j = 0; j < TN; j++)
                    acc[i][j] += regM[i] * regN[j];
        }
        __syncthreads();
    }

    const int rowBase = by * BM + tRow * TM;
    const int colBase = bx * BN + tCol * TN;
#pragma unroll
    for (int i = 0; i < TM; i++) {
#pragma unroll
        for (int j = 0; j < TN; j += 4) {
            float4 o;
            o.x = acc[i][j + 0] + bias[colBase + j + 0];
            o.y = acc[i][j + 1] + bias[colBase + j + 1];
            o.z = acc[i][j + 2] + bias[colBase + j + 2];
            o.w = acc[i][j + 3] + bias[colBase + j + 3];
            *(float4*)(C + (size_t)(rowBase + i) * N + colBase + j) = o;
        }
    }
}

__global__ __launch_bounds__(256, 2) void gemm_bias_128x128(
    const float* __restrict__ A, const float* __restrict__ W,
    const float* __restrict__ bias, float* __restrict__ C, int N, int K)
{
    gemm_body(A, W, bias, C, N, K, blockIdx.x, blockIdx.y, threadIdx.x);
}

// Fused Q/K/V projection: blockIdx.z selects which of the three GEMMs.
__global__ __launch_bounds__(256, 2) void qkv_gemm(
    const float* __restrict__ xq, const float* __restrict__ xk, const float* __restrict__ xv,
    const float* __restrict__ wq, const float* __restrict__ wk, const float* __restrict__ wv,
    const float* __restrict__ bq, const float* __restrict__ bk, const float* __restrict__ bv,
    float* __restrict__ oq, float* __restrict__ ok, float* __restrict__ ov)
{
    const int z = blockIdx.z;
    const float* A = (z == 0) ? xq : (z == 1) ? xk : xv;
    const float* W = (z == 0) ? wq : (z == 1) ? wk : wv;
    const float* b = (z == 0) ? bq : (z == 1) ? bk : bv;
    float*       C = (z == 0) ? oq : (z == 1) ? ok : ov;
    gemm_body(A, W, b, C, D_MODEL, D_MODEL, blockIdx.x, blockIdx.y, threadIdx.x);
}

// ---------------------------------------------------------------------------
// scores: S[bh,q,k] = exp(scale * dot(Q,K)) (masked -> 0), plus per-row
// partial sums over this 128-col tile (deterministic shuffle tree).
// ---------------------------------------------------------------------------
__global__ __launch_bounds__(256, 2) void scores_kernel(
    const int* __restrict__ mask, float* __restrict__ Sext, int use_ext)
{
    constexpr int BM = 128, BN = 128, BK = 32, TM = 8, TN = 8;
    __shared__ float Qs[BK][BM];
    __shared__ float Ks[BK][BN];

    float* S = use_ext ? Sext : g_attn;
    const int bh = blockIdx.z;
    const int b  = bh >> 4;
    const int h  = bh & 15;
    const int tid  = threadIdx.x;
    const int tRow = tid >> 4;
    const int tCol = tid & 15;

    const float* Qb = g_q + ((size_t)b * SEQQ + (size_t)blockIdx.y * BM) * D_MODEL + h * DHEAD;
    const float* Kb = g_k + ((size_t)b * SEQK + (size_t)blockIdx.x * BN) * D_MODEL + h * DHEAD;

    float acc[TM][TN] = {};

    for (int k0 = 0; k0 < DHEAD; k0 += BK) {
#pragma unroll
        for (int i = 0; i < 4; i++) {
            int idx = tid + i * 256;
            int row = idx >> 3;
            int cv  = (idx & 7) * 4;
            float4 q4 = *(const float4*)(Qb + (size_t)row * D_MODEL + k0 + cv);
            Qs[cv + 0][row] = q4.x; Qs[cv + 1][row] = q4.y;
            Qs[cv + 2][row] = q4.z; Qs[cv + 3][row] = q4.w;
            float4 k4 = *(const float4*)(Kb + (size_t)row * D_MODEL + k0 + cv);
            Ks[cv + 0][row] = k4.x; Ks[cv + 1][row] = k4.y;
            Ks[cv + 2][row] = k4.z; Ks[cv + 3][row] = k4.w;
        }
        __syncthreads();

#pragma unroll
        for (int k = 0; k < BK; k++) {
            float regM[TM], regN[TN];
            *(float4*)&regM[0] = *(const float4*)&Qs[k][tRow * TM];
            *(float4*)&regM[4] = *(const float4*)&Qs[k][tRow * TM + 4];
            *(float4*)&regN[0] = *(const float4*)&Ks[k][tCol * TN];
            *(float4*)&regN[4] = *(const float4*)&Ks[k][tCol * TN + 4];
#pragma unroll
            for (int i = 0; i < TM; i++)
#pragma unroll
                for (int j = 0; j < TN; j++)
                    acc[i][j] += regM[i] * regN[j];
        }
        __syncthreads();
    }

    const float scale = 0.125f;  // 64^-0.5
    const int q0 = blockIdx.y * BM + tRow * TM;
    const int c0 = blockIdx.x * BN + tCol * TN;
    float rowpart[TM];
#pragma unroll
    for (int i = 0; i < TM; i++) {
        const int q = q0 + i;
        const size_t mrow = ((size_t)b * SEQQ + q) * SEQK;
        const size_t srow = ((size_t)bh * SEQQ + q) * SEQK;
        float rp = 0.f;
#pragma unroll
        for (int j = 0; j < TN; j += 4) {
            int4 mk = *(const int4*)(mask + mrow + c0 + j);
            float4 o;
            o.x = mk.x ? __expf(acc[i][j + 0] * scale) : 0.f;
            o.y = mk.y ? __expf(acc[i][j + 1] * scale) : 0.f;
            o.z = mk.z ? __expf(acc[i][j + 2] * scale) : 0.f;
            o.w = mk.w ? __expf(acc[i][j + 3] * scale) : 0.f;
            *(float4*)(S + srow + c0 + j) = o;
            rp += (o.x + o.y) + (o.z + o.w);
        }
        rowpart[i] = rp;
    }
    // Reduce across the 16 tCol lanes (same tRow -> same 16-lane shuffle group).
#pragma unroll
    for (int i = 0; i < TM; i++) {
#pragma unroll
        for (int o = 8; o; o >>= 1)
            rowpart[i] += __shfl_xor_sync(0xffffffffu, rowpart[i], o);
    }
    if (tCol == 0) {
#pragma unroll
        for (int i = 0; i < TM; i++)
            g_partial[((size_t)bh * SEQQ + q0 + i) * KTILES + blockIdx.x] = rowpart[i];
    }
}

// ---------------------------------------------------------------------------
// Deterministic row-sum reduce: one thread per attention row.
// ---------------------------------------------------------------------------
__global__ __launch_bounds__(256) void rowsum_reduce()
{
    const int r = blockIdx.x * 256 + threadIdx.x;
    const float* p = g_partial + (size_t)r * KTILES;
    float s = 0.f;
#pragma unroll
    for (int i = 0; i < KTILES; i++) s += p[i];
    g_rowinv[r] = 1.0f / s;
}

// ---------------------------------------------------------------------------
// PV: ctx = (S @ V) * inv ; also rewrites attn <- S * inv in place (each attn
// element is read exactly once by exactly one block).
// ---------------------------------------------------------------------------
__global__ __launch_bounds__(256, 2) void pv_kernel(float* __restrict__ Sext, int use_ext)
{
    constexpr int BM = 128, BN = 64, BK = 16, TM = 8, TN = 4;
    __shared__ float Ps[BK][BM];
    __shared__ float Vs[BK][BN];
    __shared__ float invs[BM];

    float* S = use_ext ? Sext : g_attn;
    const int bh = blockIdx.z;
    const int b  = bh >> 4;
    const int h  = bh & 15;
    const int tid  = threadIdx.x;
    const int tRow = tid >> 4;
    const int tCol = tid & 15;

    const int qbase = blockIdx.x * BM;
    float* Pb = S + ((size_t)bh * SEQQ + qbase) * SEQK;
    const float* Vb = g_v + (size_t)b * SEQK * D_MODEL + h * DHEAD;

    if (tid < BM) invs[tid] = g_rowinv[(size_t)bh * SEQQ + qbase + tid];
    __syncthreads();

    float acc[TM][TN] = {};

    for (int k0 = 0; k0 < SEQK; k0 += BK) {
#pragma unroll
        for (int i = 0; i < 2; i++) {
            int idx = tid + i * 256;
            int row = idx >> 2;
            int cv  = (idx & 3) * 4;
            float* src = Pb + (size_t)row * SEQK + k0 + cv;
            float4 p4 = *(const float4*)src;
            Ps[cv + 0][row] = p4.x; Ps[cv + 1][row] = p4.y;
            Ps[cv + 2][row] = p4.z; Ps[cv + 3][row] = p4.w;
            const float inv = invs[row];
            float4 pn;
            pn.x = p4.x * inv; pn.y = p4.y * inv;
            pn.z = p4.z * inv; pn.w = p4.w * inv;
            *(float4*)src = pn;                       // normalized attn output
        }
        {
            int row = tid >> 4;
            int cv  = (tid & 15) * 4;
            *(float4*)&Vs[row][cv] =
                *(const float4*)(Vb + (size_t)(k0 + row) * D_MODEL + cv);
        }
        __syncthreads();

#pragma unroll
        for (int k = 0; k < BK; k++) {
            float regM[TM], regN[TN];
            *(float4*)&regM[0] = *(const float4*)&Ps[k][tRow * TM];
            *(float4*)&regM[4] = *(const float4*)&Ps[k][tRow * TM + 4];
            *(float4*)&regN[0] = *(const float4*)&Vs[k][tCol * TN];
#pragma unroll
            for (int i = 0; i < TM; i++)
#pragma unroll
                for (int j = 0; j < TN; j++)
                    acc[i][j] += regM[i] * regN[j];
        }
        __syncthreads();
    }

    const int q0 = qbase + tRow * TM;
    const int n0 = tCol * TN;
#pragma unroll
    for (int i = 0; i < TM; i++) {
        const float inv = invs[tRow * TM + i];
        float4 o;
        o.x = acc[i][0] * inv; o.y = acc[i][1] * inv;
        o.z = acc[i][2] * inv; o.w = acc[i][3] * inv;
        *(float4*)(g_ctx + ((size_t)b * SEQQ + q0 + i) * D_MODEL + h * DHEAD + n0) = o;
    }
}

// ---------------------------------------------------------------------------
extern "C" void kernel_launch(void* const* d_in, const int* in_sizes, int n_in,
                              void* d_out, int out_size)
{
    const float* q    = (const float*)d_in[0];
    const float* k    = (const float*)d_in[1];
    const float* v    = (const float*)d_in[2];
    const int*   mask = (const int*)  d_in[3];
    const float* w_q  = (const float*)d_in[4];
    const float* b_q  = (const float*)d_in[5];
    const float* w_k  = (const float*)d_in[6];
    const float* b_k  = (const float*)d_in[7];
    const float* w_v  = (const float*)d_in[8];
    const float* b_v  = (const float*)d_in[9];
    const float* w_o  = (const float*)d_in[10];
    const float* b_o  = (const float*)d_in[11];

    float* out = (float*)d_out;

    const size_t OUT_ELEMS  = (size_t)MTOK * D_MODEL;
    const size_t ATTN_ELEMS = (size_t)BATCH * NHEADS * SEQQ * SEQK;
    const int use_ext = ((size_t)out_size >= OUT_ELEMS + ATTN_ELEMS) ? 1 : 0;
    float* attn_ext = out + OUT_ELEMS;

    float *gq = nullptr, *gk = nullptr, *gv = nullptr, *gctx = nullptr;
    cudaGetSymbolAddress((void**)&gq,   g_q);
    cudaGetSymbolAddress((void**)&gk,   g_k);
    cudaGetSymbolAddress((void**)&gv,   g_v);
    cudaGetSymbolAddress((void**)&gctx, g_ctx);

    dim3 gqkv(D_MODEL / 128, MTOK / 128, 3);             // (8, 32, 3)
    qkv_gemm<<<gqkv, 256>>>(q, k, v, w_q, w_k, w_v, b_q, b_k, b_v, gq, gk, gv);

    dim3 gsc(SEQK / 128, SEQQ / 128, BATCH * NHEADS);    // (16, 16, 32)
    scores_kernel<<<gsc, 256>>>(mask, attn_ext, use_ext);

    rowsum_reduce<<<NROWS / 256, 256>>>();

    dim3 gpv(SEQQ / 128, 1, BATCH * NHEADS);             // (16, 1, 32)
    pv_kernel<<<gpv, 256>>>(attn_ext, use_ext);

    dim3 gproj(D_MODEL / 128, MTOK / 128);               // (8, 32)
    gemm_bias_128x128<<<gproj, 256>>>(gctx, w_o, b_o, out, D_MODEL, D_MODEL);
}